// round 9
// baseline (speedup 1.0000x reference)
#include <cuda_runtime.h>
#include <cstdint>

#define NMAX 100000
#define EMAX 3300000
#define MMAX 8192
#define KINF 0xFFFFFFFFFFFFFFFFULL
#define MAXB 1024
#define NEG0 0x80000000u

// ---------------- static device scratch (no allocations allowed) -------------
__device__ unsigned long long g_key[NMAX];
__device__ unsigned long long g_mkA[NMAX];     // masked?INF:key, parity A
__device__ unsigned long long g_mkB[NMAX];     // parity B
__device__ unsigned char g_mbA[NMAX];          // mask, parity A
__device__ unsigned char g_mbB[NMAX];          // parity B
__device__ unsigned char g_mis[NMAX];
__device__ unsigned long long g_minCur[NMAX];  // clustering only
__device__ unsigned long long g_minNew[NMAX];  // clustering only
__device__ int g_misIdx[NMAX];
__device__ int g_cluster[NMAX];
__device__ int g_nbr[EMAX];                    // in-neighbor CSR payload (rows)
__device__ int g_csrCnt[NMAX];
__device__ int g_csrOff[NMAX + 1];
__device__ int g_csrCur[NMAX];
__device__ float g_dense[(size_t)MMAX * (size_t)MMAX];   // 256 MB, NEG0 presence
__device__ int g_nodeCnt[MAXB];
__device__ int g_nodeOff[MAXB];
__device__ int g_cellCnt[MAXB];
__device__ int g_cellOff[MAXB];
__device__ int g_cnt2[2];
__device__ unsigned long long g_maxMisKey;
__device__ int g_M;
__device__ int g_P;
__device__ unsigned int g_arrive;

// ---------------- helpers ----------------------------------------------------

__device__ __forceinline__ void grid_bar(unsigned nb, unsigned &target) {
    __threadfence();
    __syncthreads();
    if (threadIdx.x == 0) {
        target += nb;
        atomicAdd(&g_arrive, 1u);
        while (*((volatile unsigned*)&g_arrive) < target) __nanosleep(32);
        __threadfence();
    }
    __syncthreads();
}

__device__ __forceinline__ int block_reduce_add(int v) {
    __shared__ int shr[32];
    int lane = threadIdx.x & 31;
    int w = threadIdx.x >> 5;
    #pragma unroll
    for (int o = 16; o; o >>= 1) v += __shfl_down_sync(0xffffffffu, v, o);
    if (lane == 0) shr[w] = v;
    __syncthreads();
    int nw = (blockDim.x + 31) >> 5;
    int r = 0;
    if (w == 0) {
        r = (lane < nw) ? shr[lane] : 0;
        #pragma unroll
        for (int o = 16; o; o >>= 1) r += __shfl_down_sync(0xffffffffu, r, o);
    }
    __syncthreads();
    return r;  // valid on threadIdx.x == 0
}

__device__ __forceinline__ int block_excl_scan(int v, int &total) {
    __shared__ int sh[1024];
    int t = threadIdx.x;
    sh[t] = v;
    __syncthreads();
    for (int off = 1; off < blockDim.x; off <<= 1) {
        int y = (t >= off) ? sh[t - off] : 0;
        __syncthreads();
        sh[t] += y;
        __syncthreads();
    }
    int incl = sh[t];
    total = sh[blockDim.x - 1];
    __syncthreads();
    return incl - v;
}

__device__ __forceinline__ unsigned long long warp_min_ull(unsigned long long m) {
    #pragma unroll
    for (int o = 16; o; o >>= 1) {
        unsigned long long t = __shfl_down_sync(0xffffffffu, m, o);
        if (t < m) m = t;
    }
    return m;  // valid on lane 0
}

// ---------------- kernels -----------------------------------------------------

__global__ void k_init(const float* __restrict__ score, int n) {
    int v = blockIdx.x * blockDim.x + threadIdx.x;
    if (v < n) {
        unsigned long long k =
            ((unsigned long long)__float_as_uint(score[v]) << 32) | (unsigned)v;
        g_key[v] = k; g_mkA[v] = k;
        g_mbA[v] = 0; g_mis[v] = 0;
        g_csrCnt[v] = 0;
    }
    if (v == 0) {
        g_arrive = 0;
        g_cnt2[0] = 0; g_cnt2[1] = 1;   // slot 1 read at top of round 0
        g_maxMisKey = 0; g_M = 0; g_P = 0;
    }
}

// Persistent kernel: CSR build + 2-barrier/round MIS loop + clustering.
__global__ void __launch_bounds__(256, 4)
k_persist(const int* __restrict__ erow, const int* __restrict__ ecol,
          int n, int e, const float* __restrict__ x, int d,
          float* __restrict__ out)
{
    const unsigned nb = gridDim.x;
    const unsigned nt = nb * blockDim.x;
    const unsigned tid = blockIdx.x * blockDim.x + threadIdx.x;
    const unsigned wid = tid >> 5;
    const unsigned lane = tid & 31;
    const unsigned nwrp = nt >> 5;
    unsigned bt = 0;
    const bool vecok = ((e & 3) == 0);
    const unsigned e4 = (unsigned)e >> 2;

    // contiguous node chunk per block (scan phases)
    const int chunk = (n + (int)nb - 1) / (int)nb;
    const int cs = (int)blockIdx.x * chunk;
    const int ce = (cs + chunk > n) ? n : cs + chunk;
    // contiguous col range per warp (gather phases)
    const unsigned cpw = ((unsigned)n + nwrp - 1) / nwrp;
    const unsigned c0 = wid * cpw;
    const unsigned c1 = (c0 + cpw > (unsigned)n) ? (unsigned)n : c0 + cpw;

    // ---------------- build in-neighbor CSR (R5-verified code) ----------------
    if (vecok) {
        for (unsigned i = tid; i < e4; i += nt) {
            int4 c = __ldg((const int4*)ecol + i);
            atomicAdd(&g_csrCnt[c.x], 1); atomicAdd(&g_csrCnt[c.y], 1);
            atomicAdd(&g_csrCnt[c.z], 1); atomicAdd(&g_csrCnt[c.w], 1);
        }
    } else {
        for (unsigned i = tid; i < (unsigned)e; i += nt)
            atomicAdd(&g_csrCnt[ecol[i]], 1);
    }
    grid_bar(nb, bt);
    {
        int s = 0;
        for (int v = cs + (int)threadIdx.x; v < ce; v += (int)blockDim.x)
            s += g_csrCnt[v];
        int bs = block_reduce_add(s);
        if (threadIdx.x == 0) g_nodeCnt[blockIdx.x] = bs;
    }
    grid_bar(nb, bt);
    if (blockIdx.x == 0 && threadIdx.x == 0) {
        int s = 0;
        for (unsigned i = 0; i < nb; ++i) { int c = g_nodeCnt[i]; g_nodeOff[i] = s; s += c; }
        g_csrOff[n] = s;
    }
    grid_bar(nb, bt);
    {
        int run = g_nodeOff[blockIdx.x];
        for (int t0 = cs; t0 < ce; t0 += (int)blockDim.x) {
            int v = t0 + (int)threadIdx.x;
            int f = (v < ce) ? g_csrCnt[v] : 0;
            int tot;
            int ex = block_excl_scan(f, tot);
            if (v < ce) { g_csrOff[v] = run + ex; g_csrCur[v] = run + ex; }
            run += tot;
        }
    }
    grid_bar(nb, bt);
    if (vecok) {
        for (unsigned i = tid; i < e4; i += nt) {
            int4 r = __ldg((const int4*)erow + i);
            int4 c = __ldg((const int4*)ecol + i);
            g_nbr[atomicAdd(&g_csrCur[c.x], 1)] = r.x;
            g_nbr[atomicAdd(&g_csrCur[c.y], 1)] = r.y;
            g_nbr[atomicAdd(&g_csrCur[c.z], 1)] = r.z;
            g_nbr[atomicAdd(&g_csrCur[c.w], 1)] = r.w;
        }
    } else {
        for (unsigned i = tid; i < (unsigned)e; i += nt)
            g_nbr[atomicAdd(&g_csrCur[ecol[i]], 1)] = erow[i];
    }
    grid_bar(nb, bt);

    // ---------------- MIS loop: 2 barriers per round ---------------------------
    for (int round = 0; round < 100000; ++round) {
        if (*((volatile int*)&g_cnt2[(round + 1) & 1]) == 0) break;
        const unsigned long long* mkC = (round & 1) ? g_mkB : g_mkA;
        unsigned long long* mkN = (round & 1) ? g_mkA : g_mkB;
        unsigned char* mbC = (round & 1) ? g_mbB : g_mbA;
        unsigned char* mbN = (round & 1) ? g_mbA : g_mbB;

        // Phase 1: unmasked col joins MIS iff its key <= min over in-nbrs of mk.
        for (unsigned col = c0; col < c1; ++col) {
            unsigned long long selfk = mkC[col];
            if (selfk == KINF) continue;              // masked: skip whole adjacency
            int s = g_csrOff[col], e2 = g_csrOff[col + 1];
            unsigned long long m = KINF;
            for (int j = s + (int)lane; j < e2; j += 32) {
                unsigned long long k = mkC[g_nbr[j]];
                if (k < m) m = k;
            }
            m = warp_min_ull(m);
            if (lane == 0 && selfk <= m) { g_mis[col] = 1; mbC[col] = 1; }
        }
        grid_bar(nb, bt);

        // Phase 2: dilate mask-after-B by exactly 1 hop; commit to next buffers.
        // (Reset of the just-checked counter slot is safe here: the barrier above
        //  guarantees every block already performed this round's loop-top check.)
        if (tid == 0) g_cnt2[(round + 1) & 1] = 0;
        {
            int myUn = 0;
            for (unsigned col = c0; col < c1; ++col) {
                int nm;
                if (mbC[col]) nm = 1;
                else {
                    int s = g_csrOff[col], e2 = g_csrOff[col + 1];
                    int a = 0;
                    for (int j = s + (int)lane; j < e2; j += 32)
                        a |= mbC[g_nbr[j]];
                    nm = __any_sync(0xffffffffu, a);
                }
                if (lane == 0) {
                    mkN[col] = nm ? KINF : g_key[col];
                    mbN[col] = (unsigned char)nm;
                    myUn += (nm == 0);
                }
            }
            if (lane == 0 && myUn) atomicAdd(&g_cnt2[round & 1], myUn);
        }
        grid_bar(nb, bt);
    }

    // ---------------- clustering ---------------------------------------------
    for (unsigned v = tid; v < (unsigned)n; v += nt) {
        unsigned long long mc;
        if (g_mis[v]) { mc = g_key[v]; atomicMax(&g_maxMisKey, mc); }
        else mc = KINF;
        g_minCur[v] = mc;
    }
    {
        int cnt = 0;
        for (int v = cs + (int)threadIdx.x; v < ce; v += (int)blockDim.x)
            cnt += g_mis[v];
        int bs = block_reduce_add(cnt);
        if (threadIdx.x == 0) g_nodeCnt[blockIdx.x] = bs;
    }
    grid_bar(nb, bt);

    if (blockIdx.x == 0 && threadIdx.x == 0) {
        int s = 0;
        for (unsigned i = 0; i < nb; ++i) { int c = g_nodeCnt[i]; g_nodeOff[i] = s; s += c; }
        if (s > MMAX) s = MMAX;
        g_M = s;
    }
    grid_bar(nb, bt);

    {
        int run = g_nodeOff[blockIdx.x];
        for (int t0 = cs; t0 < ce; t0 += (int)blockDim.x) {
            int v = t0 + (int)threadIdx.x;
            int f = (v < ce) ? (int)g_mis[v] : 0;
            int tot;
            int ex = block_excl_scan(f, tot);
            if (v < ce) g_misIdx[v] = run + ex;
            run += tot;
        }
    }
    grid_bar(nb, bt);

    // H: one min-key propagation (k = 1), warp-per-col CSR gather, no atomics
    for (unsigned col = c0; col < c1; ++col) {
        int s = g_csrOff[col], e2 = g_csrOff[col + 1];
        unsigned long long m = g_minCur[col];         // self seed
        for (int j = s + (int)lane; j < e2; j += 32) {
            unsigned long long k = g_minCur[g_nbr[j]];
            if (k < m) m = k;
        }
        m = warp_min_ull(m);
        if (lane == 0) g_minNew[col] = m;
    }
    grid_bar(nb, bt);

    // I: cluster assignment (low 32 bits of winning key = MIS node index)
    int fb = g_misIdx[(unsigned)(g_maxMisKey & 0xffffffffULL)];
    for (unsigned v = tid; v < (unsigned)n; v += nt) {
        unsigned long long mk = g_minNew[v];
        g_cluster[v] = (mk == KINF) ? fb : g_misIdx[(unsigned)(mk & 0xffffffffULL)];
    }

    // J: x_out = x[mis]
    if ((d & 3) == 0) {
        int dv = d >> 2;
        for (unsigned v = tid; v < (unsigned)n; v += nt) {
            if (g_mis[v]) {
                const float4* src = (const float4*)(x + (size_t)v * d);
                float4* dst = (float4*)(out + (size_t)g_misIdx[v] * d);
                for (int j = 0; j < dv; ++j) dst[j] = src[j];
            }
        }
    } else {
        for (unsigned v = tid; v < (unsigned)n; v += nt) {
            if (g_mis[v]) {
                const float* src = x + (size_t)v * d;
                float* dst = out + (size_t)g_misIdx[v] * d;
                for (int j = 0; j < d; ++j) dst[j] = src[j];
            }
        }
    }
}

// ---------------- dense pipeline (proven, NEG0 presence) ----------------------

__global__ void k_zero() {
    size_t MM = (size_t)g_M * (size_t)g_M;
    size_t nt = (size_t)gridDim.x * blockDim.x;
    float neg0 = __uint_as_float(NEG0);
    for (size_t i = (size_t)blockIdx.x * blockDim.x + threadIdx.x; i < MM; i += nt)
        g_dense[i] = neg0;
}

__global__ void k_accum(const int* __restrict__ erow, const int* __restrict__ ecol,
                        const float* __restrict__ attr, int e) {
    unsigned M = (unsigned)g_M;
    unsigned nt = gridDim.x * blockDim.x;
    unsigned t = blockIdx.x * blockDim.x + threadIdx.x;
    if ((e & 3) == 0) {
        unsigned e4 = (unsigned)e >> 2;
        for (unsigned i = t; i < e4; i += nt) {
            int4 r = __ldg((const int4*)erow + i);
            int4 c = __ldg((const int4*)ecol + i);
            float4 a = __ldg((const float4*)attr + i);
            unsigned i0 = (unsigned)g_cluster[r.x] * M + (unsigned)g_cluster[c.x];
            unsigned i1 = (unsigned)g_cluster[r.y] * M + (unsigned)g_cluster[c.y];
            unsigned i2 = (unsigned)g_cluster[r.z] * M + (unsigned)g_cluster[c.z];
            unsigned i3 = (unsigned)g_cluster[r.w] * M + (unsigned)g_cluster[c.w];
            atomicAdd(&g_dense[i0], a.x);
            atomicAdd(&g_dense[i1], a.y);
            atomicAdd(&g_dense[i2], a.z);
            atomicAdd(&g_dense[i3], a.w);
        }
    } else {
        for (unsigned i = t; i < (unsigned)e; i += nt) {
            unsigned idx = (unsigned)g_cluster[erow[i]] * M + (unsigned)g_cluster[ecol[i]];
            atomicAdd(&g_dense[idx], attr[i]);
        }
    }
}

__global__ void k_count() {
    unsigned M = (unsigned)g_M;
    size_t MM = (size_t)M * M;
    size_t chunk = (MM + gridDim.x - 1) / gridDim.x;
    size_t s = (size_t)blockIdx.x * chunk;
    size_t epos = s + chunk; if (epos > MM) epos = MM;
    int cnt = 0;
    for (size_t i = s + threadIdx.x; i < epos; i += blockDim.x) {
        if (__float_as_uint(g_dense[i]) != NEG0) {
            unsigned ii = (unsigned)i;
            unsigned r = ii / M, c = ii - r * M;
            cnt += (r != c);
        }
    }
    int bs = block_reduce_add(cnt);
    if (threadIdx.x == 0) g_cellCnt[blockIdx.x] = bs;
}

__global__ void k_scan(int nb2) {
    int t = threadIdx.x;
    int v = (t < nb2) ? g_cellCnt[t] : 0;
    int tot;
    int ex = block_excl_scan(v, tot);
    if (t < nb2) g_cellOff[t] = ex;
    if (t == 0) g_P = tot;
}

__global__ void k_write(float* __restrict__ out, int d) {
    unsigned M = (unsigned)g_M;
    size_t MM = (size_t)M * M;
    size_t P = (size_t)g_P;
    size_t xoff = (size_t)M * (size_t)d;
    size_t chunk = (MM + gridDim.x - 1) / gridDim.x;
    size_t s = (size_t)blockIdx.x * chunk;
    size_t epos = s + chunk; if (epos > MM) epos = MM;
    size_t base = (size_t)g_cellOff[blockIdx.x];
    for (size_t t0 = s; t0 < epos; t0 += blockDim.x) {
        size_t i = t0 + threadIdx.x;
        int keep = 0; unsigned r = 0, c = 0; float val = 0.f;
        if (i < epos) {
            float fv = g_dense[i];
            if (__float_as_uint(fv) != NEG0) {
                unsigned ii = (unsigned)i;
                r = ii / M; c = ii - r * M;
                if (r != c) { keep = 1; val = fv; }
            }
        }
        int tot;
        int ex = block_excl_scan(keep, tot);
        if (keep) {
            size_t p = base + (size_t)ex;
            out[xoff + p] = (float)r;
            out[xoff + P + p] = (float)c;
            out[xoff + 2 * P + p] = val;
        }
        base += tot;
    }
}

__global__ void k_tail(float* __restrict__ out, const float* __restrict__ score,
                       int n, int d) {
    int v = blockIdx.x * blockDim.x + threadIdx.x;
    if (v >= n) return;
    size_t off = (size_t)g_M * (size_t)d + 3 * (size_t)g_P;
    out[off + v] = (float)g_cluster[v];
    out[off + (size_t)n + v] = g_mis[v] ? 1.0f : 0.0f;
    out[off + 2 * (size_t)n + v] = score[v];
}

// ---------------- entry -------------------------------------------------------
extern "C" void kernel_launch(void* const* d_in, const int* in_sizes, int n_in,
                              void* d_out, int out_size) {
    const float* x = (const float*)d_in[0];
    const int* ei = (const int*)d_in[1];
    const float* attr = (const float*)d_in[2];
    const float* score = (const float*)d_in[3];
    int n = in_sizes[3];
    int e = in_sizes[1] / 2;
    int d = in_sizes[0] / n;
    const int* erow = ei;
    const int* ecol = ei + e;
    float* out = (float*)d_out;

    int dev = 0;
    cudaGetDevice(&dev);
    int sms = 148;
    cudaDeviceGetAttribute(&sms, cudaDevAttrMultiProcessorCount, dev);
    int nb = sms * 2;                 // fewer blocks -> cheaper grid barriers
    if (nb > MAXB) nb = MAXB;

    k_init<<<(n + 255) / 256, 256>>>(score, n);
    k_persist<<<nb, 256>>>(erow, ecol, n, e, x, d, out);
    k_zero<<<2048, 256>>>();
    k_accum<<<sms * 8, 256>>>(erow, ecol, attr, e);
    k_count<<<MAXB, 256>>>();
    k_scan<<<1, 1024>>>(MAXB);
    k_write<<<MAXB, 256>>>(out, d);
    k_tail<<<(n + 255) / 256, 256>>>(out, score, n, d);
}